// round 1
// baseline (speedup 1.0000x reference)
#include <cuda_runtime.h>

// Problem constants (fixed by reference_code)
#define Bsz 4
#define Ssz 2048
#define Hn  16
#define DKk 64
#define Dm  1024
#define Mrows (Bsz*Ssz)   // 8192

// Scratch (allocation-free rule: __device__ globals)
__device__ __align__(128) float g_Q[(size_t)Bsz*Hn*Ssz*DKk];     // [B,H,S,dk]
__device__ __align__(128) float g_K[(size_t)Bsz*Hn*Ssz*DKk];
__device__ __align__(128) float g_V[(size_t)Bsz*Hn*Ssz*DKk];
__device__ __align__(128) float g_attn[(size_t)Mrows*Dm];        // [B*S, D]

// ---------------------------------------------------------------------------
// NT GEMM: C[m,n] = sum_k X[m,k] * W[n,k] + bias[n]
// X: [M,K] row-major, W: [N,K] row-major (torch Linear weight), K=N=1024.
// Tile 128x128xk8, 256 threads, 8x8 per-thread microtile.
// qkv_layout=1 writes into [B,H,S,dk] head-split layout, else plain [M,N].
// ---------------------------------------------------------------------------
__device__ __forceinline__ void gemm_body(const float* __restrict__ X,
                                          const float* __restrict__ W,
                                          const float* __restrict__ bias,
                                          float* __restrict__ out,
                                          int qkv_layout)
{
    __shared__ float As[8][128];
    __shared__ float Bs[8][128];
    const int K = Dm;

    int tid  = threadIdx.x;
    int bm   = blockIdx.y * 128;
    int bn   = blockIdx.x * 128;
    int lrow = tid >> 1;          // 0..127
    int lk   = (tid & 1) * 4;     // 0 or 4
    int ty   = tid >> 4;          // 0..15
    int tx   = tid & 15;          // 0..15

    float acc[8][8];
#pragma unroll
    for (int i = 0; i < 8; i++)
#pragma unroll
        for (int j = 0; j < 8; j++) acc[i][j] = 0.f;

    const float* Xp = X + (size_t)(bm + lrow) * K + lk;
    const float* Wp = W + (size_t)(bn + lrow) * K + lk;

    for (int k0 = 0; k0 < K; k0 += 8) {
        float4 a = *(const float4*)(Xp + k0);
        float4 b = *(const float4*)(Wp + k0);
        __syncthreads();   // previous compute finished reading smem
        As[lk+0][lrow] = a.x; As[lk+1][lrow] = a.y;
        As[lk+2][lrow] = a.z; As[lk+3][lrow] = a.w;
        Bs[lk+0][lrow] = b.x; Bs[lk+1][lrow] = b.y;
        Bs[lk+2][lrow] = b.z; Bs[lk+3][lrow] = b.w;
        __syncthreads();   // tile visible

#pragma unroll
        for (int kk = 0; kk < 8; kk++) {
            float4 a0 = *(const float4*)&As[kk][ty*8];
            float4 a1 = *(const float4*)&As[kk][ty*8+4];
            float4 b0 = *(const float4*)&Bs[kk][tx*8];
            float4 b1 = *(const float4*)&Bs[kk][tx*8+4];
            float ar[8] = {a0.x,a0.y,a0.z,a0.w,a1.x,a1.y,a1.z,a1.w};
            float br[8] = {b0.x,b0.y,b0.z,b0.w,b1.x,b1.y,b1.z,b1.w};
#pragma unroll
            for (int i = 0; i < 8; i++)
#pragma unroll
                for (int j = 0; j < 8; j++)
                    acc[i][j] += ar[i] * br[j];
        }
    }

    if (qkv_layout) {
#pragma unroll
        for (int i = 0; i < 8; i++) {
            int m = bm + ty*8 + i;
            int b = m >> 11;            // /S
            int s = m & (Ssz - 1);
#pragma unroll
            for (int j = 0; j < 8; j += 4) {
                int n = bn + tx*8 + j;  // h*64+d; stays within one head per float4
                int h = n >> 6;
                int d = n & 63;
                float4 v;
                v.x = acc[i][j+0] + bias[n+0];
                v.y = acc[i][j+1] + bias[n+1];
                v.z = acc[i][j+2] + bias[n+2];
                v.w = acc[i][j+3] + bias[n+3];
                *(float4*)&out[((size_t)((b*Hn + h)*Ssz + s))*DKk + d] = v;
            }
        }
    } else {
#pragma unroll
        for (int i = 0; i < 8; i++) {
            size_t m = (size_t)(bm + ty*8 + i);
#pragma unroll
            for (int j = 0; j < 8; j += 4) {
                int n = bn + tx*8 + j;
                float4 v;
                v.x = acc[i][j+0] + bias[n+0];
                v.y = acc[i][j+1] + bias[n+1];
                v.z = acc[i][j+2] + bias[n+2];
                v.w = acc[i][j+3] + bias[n+3];
                *(float4*)&out[m*Dm + n] = v;
            }
        }
    }
}

__global__ __launch_bounds__(256) void gemm_qkv(
    const float* __restrict__ Xq, const float* __restrict__ Xk, const float* __restrict__ Xv,
    const float* __restrict__ Wq, const float* __restrict__ Wk, const float* __restrict__ Wv,
    const float* __restrict__ bq, const float* __restrict__ bk, const float* __restrict__ bv)
{
    const float* X = Xq; const float* W = Wq; const float* bias = bq; float* out = g_Q;
    if (blockIdx.z == 1)      { X = Xk; W = Wk; bias = bk; out = g_K; }
    else if (blockIdx.z == 2) { X = Xv; W = Wv; bias = bv; out = g_V; }
    gemm_body(X, W, bias, out, 1);
}

__global__ __launch_bounds__(256) void gemm_out(
    const float* __restrict__ W, const float* __restrict__ bias, float* __restrict__ out)
{
    gemm_body(g_attn, W, bias, out, 0);
}

// ---------------------------------------------------------------------------
// Flash attention, fp32. One CTA = (bh, 64 query rows), one thread = one row.
// Online softmax entirely thread-local (no cross-thread reduction).
// K/V staged in smem, 32 keys per tile; scores parked in smem so the
// o-rescale is once per tile.
// ---------------------------------------------------------------------------
__global__ __launch_bounds__(64) void attn_kernel()
{
    __shared__ float Ks[32][64];
    __shared__ float Vs[32][64];
    __shared__ float Ss[64][33];   // pad -> conflict-free per-thread rows

    int bh = blockIdx.y;               // b*16 + h
    int qb = blockIdx.x * 64;          // query row base within sequence
    int t  = threadIdx.x;              // 0..63, owns q row (qb+t)

    const float* Qb = g_Q + (size_t)bh * Ssz * DKk;
    const float* Kb = g_K + (size_t)bh * Ssz * DKk;
    const float* Vb = g_V + (size_t)bh * Ssz * DKk;

    float q[64], o[64];
#pragma unroll
    for (int d4 = 0; d4 < 16; d4++) {
        float4 v = *(const float4*)&Qb[(size_t)(qb + t)*DKk + d4*4];
        q[d4*4+0] = v.x * 0.125f;      // 1/sqrt(64) folded into q
        q[d4*4+1] = v.y * 0.125f;
        q[d4*4+2] = v.z * 0.125f;
        q[d4*4+3] = v.w * 0.125f;
    }
#pragma unroll
    for (int d = 0; d < 64; d++) o[d] = 0.f;
    float m = -1e30f, l = 0.f;

    for (int j0 = 0; j0 < Ssz; j0 += 32) {
        __syncthreads();
        // cooperative tile load: 512 float4 per tile pair, 8 per thread, coalesced
#pragma unroll
        for (int i = 0; i < 8; i++) {
            int idx = i*64 + t;
            int r = idx >> 4;
            int c = (idx & 15) * 4;
            *(float4*)&Ks[r][c] = *(const float4*)&Kb[(size_t)(j0 + r)*DKk + c];
            *(float4*)&Vs[r][c] = *(const float4*)&Vb[(size_t)(j0 + r)*DKk + c];
        }
        __syncthreads();

        // scores for this tile + tile max
        float mt = -1e30f;
#pragma unroll 2
        for (int j = 0; j < 32; j++) {
            float s0 = 0.f, s1 = 0.f, s2 = 0.f, s3 = 0.f;
#pragma unroll
            for (int d4 = 0; d4 < 16; d4++) {
                float4 kv = *(const float4*)&Ks[j][d4*4];
                s0 += q[d4*4+0] * kv.x;
                s1 += q[d4*4+1] * kv.y;
                s2 += q[d4*4+2] * kv.z;
                s3 += q[d4*4+3] * kv.w;
            }
            float s = (s0 + s1) + (s2 + s3);
            Ss[t][j] = s;
            mt = fmaxf(mt, s);
        }

        float mnew = fmaxf(m, mt);
        float corr = __expf(m - mnew);
        m = mnew;
        l *= corr;
#pragma unroll
        for (int d = 0; d < 64; d++) o[d] *= corr;

        // probabilities + PV accumulate
#pragma unroll 2
        for (int j = 0; j < 32; j++) {
            float p = __expf(Ss[t][j] - mnew);
            l += p;
#pragma unroll
            for (int d4 = 0; d4 < 16; d4++) {
                float4 vv = *(const float4*)&Vs[j][d4*4];
                o[d4*4+0] += p * vv.x;
                o[d4*4+1] += p * vv.y;
                o[d4*4+2] += p * vv.z;
                o[d4*4+3] += p * vv.w;
            }
        }
    }

    float inv = 1.f / l;
    int b = bh >> 4, h = bh & 15;
    float* dst = g_attn + (size_t)(b*Ssz + qb + t)*Dm + h*DKk;
#pragma unroll
    for (int d4 = 0; d4 < 16; d4++) {
        float4 v;
        v.x = o[d4*4+0]*inv; v.y = o[d4*4+1]*inv;
        v.z = o[d4*4+2]*inv; v.w = o[d4*4+3]*inv;
        *(float4*)&dst[d4*4] = v;
    }
}

// ---------------------------------------------------------------------------
extern "C" void kernel_launch(void* const* d_in, const int* in_sizes, int n_in,
                              void* d_out, int out_size)
{
    const float* query = (const float*)d_in[0];
    const float* key_  = (const float*)d_in[1];
    const float* value = (const float*)d_in[2];
    const float* w_q   = (const float*)d_in[3];
    const float* b_q   = (const float*)d_in[4];
    const float* w_k   = (const float*)d_in[5];
    const float* b_k   = (const float*)d_in[6];
    const float* w_v   = (const float*)d_in[7];
    const float* b_v   = (const float*)d_in[8];
    const float* w_o   = (const float*)d_in[9];
    const float* b_o   = (const float*)d_in[10];
    float* out = (float*)d_out;

    // 1) QKV projections into head-split scratch: grid (N/128, M/128, 3)
    gemm_qkv<<<dim3(8, 64, 3), 256>>>(query, key_, value,
                                      w_q, w_k, w_v,
                                      b_q, b_k, b_v);

    // 2) attention: grid (S/64 q-tiles, B*H)
    attn_kernel<<<dim3(32, 64), 64>>>();

    // 3) output projection -> d_out
    gemm_out<<<dim3(8, 64), 256>>>(w_o, b_o, out);
}

// round 3
// speedup vs baseline: 1.4404x; 1.4404x over previous
#include <cuda_runtime.h>
#include <cstdint>

// Problem constants
#define Bsz 4
#define Ssz 2048
#define Hn  16
#define DKk 64
#define Dm  1024
#define Mrows (Bsz*Ssz)   // 8192

// ---------------- scratch (__device__ globals; allocation-free rule) -------
__device__ __align__(1024) float g_Q[(size_t)Bsz*Hn*Ssz*DKk];     // [B,H,S,dk]
__device__ __align__(1024) float g_K[(size_t)Bsz*Hn*Ssz*DKk];
__device__ __align__(1024) float g_V[(size_t)Bsz*Hn*Ssz*DKk];
__device__ __align__(1024) float g_attn[(size_t)Mrows*Dm];        // [B*S, D] (tf32-rounded)
// tf32-rounded copies of GEMM inputs
__device__ __align__(1024) float g_Xq[(size_t)Mrows*Dm];
__device__ __align__(1024) float g_Xk[(size_t)Mrows*Dm];
__device__ __align__(1024) float g_Xv[(size_t)Mrows*Dm];
__device__ __align__(1024) float g_Wq[(size_t)Dm*Dm];
__device__ __align__(1024) float g_Wk[(size_t)Dm*Dm];
__device__ __align__(1024) float g_Wv[(size_t)Dm*Dm];
__device__ __align__(1024) float g_Wo[(size_t)Dm*Dm];

// ---------------- helpers ----------------------------------------------
__device__ __forceinline__ uint32_t smem_u32(const void* p) {
    uint32_t a;
    asm("{ .reg .u64 t; cvta.to.shared.u64 t, %1; cvt.u32.u64 %0, t; }" : "=r"(a) : "l"(p));
    return a;
}
__device__ __forceinline__ void cp_async16(uint32_t dst, const void* src) {
    asm volatile("cp.async.cg.shared.global [%0], [%1], 16;" :: "r"(dst), "l"(src));
}
#define CP_COMMIT() asm volatile("cp.async.commit_group;" ::: "memory")
#define CP_WAIT0()  asm volatile("cp.async.wait_group 0;" ::: "memory")

// ---------------------------------------------------------------------------
// mma.sync tf32 NT GEMM: out[m,n] = sum_k X[m,k]*W[n,k] + bias[n]
// M=8192, N=K=1024. CTA 128x128x32, 8 warps (2x4), warp tile 64x32.
// SMEM [128][36] padded rows, double buffered, cp.async fill.
// layout: 0 = plain [M, Dm]; 1 = head-split [B,H,S,dk]
// ---------------------------------------------------------------------------
#define LDA 36
#define GEMM_SMEM_BYTES (4 * 4608 * 4)   // 73728 B

__device__ __forceinline__ void gemm_mma_body(const float* __restrict__ X,
                                              const float* __restrict__ W,
                                              const float* __restrict__ bias,
                                              float* __restrict__ out,
                                              int layout)
{
    extern __shared__ float sm[];
    float* Abuf[2] = { sm,        sm + 4608 };
    float* Bbuf[2] = { sm + 9216, sm + 13824 };

    const int tid  = threadIdx.x;
    const int lane = tid & 31, wid = tid >> 5;
    const int wm   = wid >> 2, wn = wid & 3;      // 2 x 4 warp grid
    const int g    = lane >> 2, q = lane & 3;
    const int bm   = blockIdx.y * 128;
    const int bn   = blockIdx.x * 128;

    float acc[4][4][4];
#pragma unroll
    for (int i = 0; i < 4; i++)
#pragma unroll
        for (int j = 0; j < 4; j++)
#pragma unroll
            for (int k = 0; k < 4; k++) acc[i][j][k] = 0.f;

    // 16 fragments of 16B per thread per (A+B) tile
    auto issue_tile = [&](int kt, int buf) {
#pragma unroll
        for (int i = 0; i < 4; i++) {
            int idx = i * 256 + tid;
            int r = idx >> 3, c4 = idx & 7;
            cp_async16(smem_u32(&Abuf[buf][r * LDA + c4 * 4]),
                       X + (size_t)(bm + r) * Dm + kt * 32 + c4 * 4);
        }
#pragma unroll
        for (int i = 0; i < 4; i++) {
            int idx = i * 256 + tid;
            int r = idx >> 3, c4 = idx & 7;
            cp_async16(smem_u32(&Bbuf[buf][r * LDA + c4 * 4]),
                       W + (size_t)(bn + r) * Dm + kt * 32 + c4 * 4);
        }
        CP_COMMIT();
    };

    issue_tile(0, 0);
    CP_WAIT0();
    __syncthreads();

    const int NT = Dm / 32;   // 32 k-tiles
    for (int kt = 0; kt < NT; kt++) {
        int buf = kt & 1;
        if (kt + 1 < NT) issue_tile(kt + 1, buf ^ 1);

        const float* Ab = Abuf[buf];
        const float* Bb = Bbuf[buf];
#pragma unroll
        for (int ks = 0; ks < 4; ks++) {
            uint32_t afr[4][4], bfr[4][2];
#pragma unroll
            for (int mt = 0; mt < 4; mt++) {
                const float* pa = Ab + (wm * 64 + mt * 16 + g) * LDA + ks * 8 + q;
                afr[mt][0] = __float_as_uint(pa[0]);
                afr[mt][1] = __float_as_uint(pa[8 * LDA]);
                afr[mt][2] = __float_as_uint(pa[4]);
                afr[mt][3] = __float_as_uint(pa[8 * LDA + 4]);
            }
#pragma unroll
            for (int nt = 0; nt < 4; nt++) {
                const float* pb = Bb + (wn * 32 + nt * 8 + g) * LDA + ks * 8 + q;
                bfr[nt][0] = __float_as_uint(pb[0]);
                bfr[nt][1] = __float_as_uint(pb[4]);
            }
#pragma unroll
            for (int mt = 0; mt < 4; mt++)
#pragma unroll
                for (int nt = 0; nt < 4; nt++) {
                    asm volatile(
                        "mma.sync.aligned.m16n8k8.row.col.f32.tf32.tf32.f32 "
                        "{%0,%1,%2,%3}, {%4,%5,%6,%7}, {%8,%9}, {%0,%1,%2,%3};"
                        : "+f"(acc[mt][nt][0]), "+f"(acc[mt][nt][1]),
                          "+f"(acc[mt][nt][2]), "+f"(acc[mt][nt][3])
                        : "r"(afr[mt][0]), "r"(afr[mt][1]), "r"(afr[mt][2]), "r"(afr[mt][3]),
                          "r"(bfr[nt][0]), "r"(bfr[nt][1]));
                }
        }
        if (kt + 1 < NT) { CP_WAIT0(); __syncthreads(); }
    }

    // epilogue: c0,c1 at (row, n..n+1); c2,c3 at (row+8, n..n+1)
#pragma unroll
    for (int mt = 0; mt < 4; mt++) {
        int r0 = bm + wm * 64 + mt * 16 + g;
#pragma unroll
        for (int nt = 0; nt < 4; nt++) {
            int n = bn + wn * 32 + nt * 8 + q * 2;
            float2 v0, v1;
            v0.x = acc[mt][nt][0] + bias[n];
            v0.y = acc[mt][nt][1] + bias[n + 1];
            v1.x = acc[mt][nt][2] + bias[n];
            v1.y = acc[mt][nt][3] + bias[n + 1];
            if (layout) {
                int h = n >> 6, d = n & 63;
                int b0i = r0 >> 11, s0 = r0 & (Ssz - 1);
                int r1 = r0 + 8;
                int b1i = r1 >> 11, s1 = r1 & (Ssz - 1);
                *(float2*)&out[((size_t)((b0i * Hn + h) * Ssz + s0)) * DKk + d] = v0;
                *(float2*)&out[((size_t)((b1i * Hn + h) * Ssz + s1)) * DKk + d] = v1;
            } else {
                *(float2*)&out[(size_t)r0 * Dm + n] = v0;
                *(float2*)&out[(size_t)(r0 + 8) * Dm + n] = v1;
            }
        }
    }
}

__global__ __launch_bounds__(256, 2) void gemm_qkv_tc(const float* __restrict__ bq,
                                                      const float* __restrict__ bk,
                                                      const float* __restrict__ bv)
{
    const float* X; const float* W; const float* bias; float* out;
    if (blockIdx.z == 0)      { X = g_Xq; W = g_Wq; bias = bq; out = g_Q; }
    else if (blockIdx.z == 1) { X = g_Xk; W = g_Wk; bias = bk; out = g_K; }
    else                      { X = g_Xv; W = g_Wv; bias = bv; out = g_V; }
    gemm_mma_body(X, W, bias, out, 1);
}

__global__ __launch_bounds__(256, 2) void gemm_out_tc(const float* __restrict__ bo,
                                                      float* __restrict__ out)
{
    gemm_mma_body(g_attn, g_Wo, bo, out, 0);
}

// ---------------------------------------------------------------------------
// tf32 RN pre-rounding (unbiased) of GEMM inputs
// ---------------------------------------------------------------------------
__global__ __launch_bounds__(256) void round_tf32_kern(const float* __restrict__ s,
                                                       float* __restrict__ d, int n4)
{
    int i = blockIdx.x * blockDim.x + threadIdx.x;
    if (i >= n4) return;
    float4 v = ((const float4*)s)[i];
    uint32_t a, b, c, e;
    asm("cvt.rna.tf32.f32 %0, %1;" : "=r"(a) : "f"(v.x));
    asm("cvt.rna.tf32.f32 %0, %1;" : "=r"(b) : "f"(v.y));
    asm("cvt.rna.tf32.f32 %0, %1;" : "=r"(c) : "f"(v.z));
    asm("cvt.rna.tf32.f32 %0, %1;" : "=r"(e) : "f"(v.w));
    float4 o;
    o.x = __uint_as_float(a); o.y = __uint_as_float(b);
    o.z = __uint_as_float(c); o.w = __uint_as_float(e);
    ((float4*)d)[i] = o;
}

// ---------------------------------------------------------------------------
// Flash attention, fp32 SIMT; epilogue writes tf32-RN-rounded values so the
// out-proj tf32 MMA sees exact operands.
// ---------------------------------------------------------------------------
__global__ __launch_bounds__(64) void attn_kernel()
{
    __shared__ float Ks[32][64];
    __shared__ float Vs[32][64];
    __shared__ float Ss[64][33];

    int bh = blockIdx.y;
    int qb = blockIdx.x * 64;
    int t  = threadIdx.x;

    const float* Qb = g_Q + (size_t)bh * Ssz * DKk;
    const float* Kb = g_K + (size_t)bh * Ssz * DKk;
    const float* Vb = g_V + (size_t)bh * Ssz * DKk;

    float q[64], o[64];
#pragma unroll
    for (int d4 = 0; d4 < 16; d4++) {
        float4 v = *(const float4*)&Qb[(size_t)(qb + t)*DKk + d4*4];
        q[d4*4+0] = v.x * 0.125f;
        q[d4*4+1] = v.y * 0.125f;
        q[d4*4+2] = v.z * 0.125f;
        q[d4*4+3] = v.w * 0.125f;
    }
#pragma unroll
    for (int d = 0; d < 64; d++) o[d] = 0.f;
    float m = -1e30f, l = 0.f;

    for (int j0 = 0; j0 < Ssz; j0 += 32) {
        __syncthreads();
#pragma unroll
        for (int i = 0; i < 8; i++) {
            int idx = i*64 + t;
            int r = idx >> 4;
            int c = (idx & 15) * 4;
            *(float4*)&Ks[r][c] = *(const float4*)&Kb[(size_t)(j0 + r)*DKk + c];
            *(float4*)&Vs[r][c] = *(const float4*)&Vb[(size_t)(j0 + r)*DKk + c];
        }
        __syncthreads();

        float mt = -1e30f;
#pragma unroll 2
        for (int j = 0; j < 32; j++) {
            float s0 = 0.f, s1 = 0.f, s2 = 0.f, s3 = 0.f;
#pragma unroll
            for (int d4 = 0; d4 < 16; d4++) {
                float4 kv = *(const float4*)&Ks[j][d4*4];
                s0 += q[d4*4+0] * kv.x;
                s1 += q[d4*4+1] * kv.y;
                s2 += q[d4*4+2] * kv.z;
                s3 += q[d4*4+3] * kv.w;
            }
            float s = (s0 + s1) + (s2 + s3);
            Ss[t][j] = s;
            mt = fmaxf(mt, s);
        }

        float mnew = fmaxf(m, mt);
        float corr = __expf(m - mnew);
        m = mnew;
        l *= corr;
#pragma unroll
        for (int d = 0; d < 64; d++) o[d] *= corr;

#pragma unroll 2
        for (int j = 0; j < 32; j++) {
            float p = __expf(Ss[t][j] - mnew);
            l += p;
#pragma unroll
            for (int d4 = 0; d4 < 16; d4++) {
                float4 vv = *(const float4*)&Vs[j][d4*4];
                o[d4*4+0] += p * vv.x;
                o[d4*4+1] += p * vv.y;
                o[d4*4+2] += p * vv.z;
                o[d4*4+3] += p * vv.w;
            }
        }
    }

    float inv = 1.f / l;
    int b = bh >> 4, h = bh & 15;
    float* dst = g_attn + (size_t)(b*Ssz + qb + t)*Dm + h*DKk;
#pragma unroll
    for (int d4 = 0; d4 < 16; d4++) {
        uint32_t ra, rb, rc, rd;
        asm("cvt.rna.tf32.f32 %0, %1;" : "=r"(ra) : "f"(o[d4*4+0]*inv));
        asm("cvt.rna.tf32.f32 %0, %1;" : "=r"(rb) : "f"(o[d4*4+1]*inv));
        asm("cvt.rna.tf32.f32 %0, %1;" : "=r"(rc) : "f"(o[d4*4+2]*inv));
        asm("cvt.rna.tf32.f32 %0, %1;" : "=r"(rd) : "f"(o[d4*4+3]*inv));
        float4 v;
        v.x = __uint_as_float(ra); v.y = __uint_as_float(rb);
        v.z = __uint_as_float(rc); v.w = __uint_as_float(rd);
        *(float4*)&dst[d4*4] = v;
    }
}

// ---------------------------------------------------------------------------
extern "C" void kernel_launch(void* const* d_in, const int* in_sizes, int n_in,
                              void* d_out, int out_size)
{
    const float* query = (const float*)d_in[0];
    const float* key_  = (const float*)d_in[1];
    const float* value = (const float*)d_in[2];
    const float* w_q   = (const float*)d_in[3];
    const float* b_q   = (const float*)d_in[4];
    const float* w_k   = (const float*)d_in[5];
    const float* b_k   = (const float*)d_in[6];
    const float* w_v   = (const float*)d_in[7];
    const float* b_v   = (const float*)d_in[8];
    const float* w_o   = (const float*)d_in[9];
    const float* b_o   = (const float*)d_in[10];
    float* out = (float*)d_out;

    cudaFuncSetAttribute(gemm_qkv_tc, cudaFuncAttributeMaxDynamicSharedMemorySize, GEMM_SMEM_BYTES);
    cudaFuncSetAttribute(gemm_out_tc, cudaFuncAttributeMaxDynamicSharedMemorySize, GEMM_SMEM_BYTES);

    float *dXq, *dXk, *dXv, *dWq, *dWk, *dWv, *dWo;
    cudaGetSymbolAddress((void**)&dXq, g_Xq);
    cudaGetSymbolAddress((void**)&dXk, g_Xk);
    cudaGetSymbolAddress((void**)&dXv, g_Xv);
    cudaGetSymbolAddress((void**)&dWq, g_Wq);
    cudaGetSymbolAddress((void**)&dWk, g_Wk);
    cudaGetSymbolAddress((void**)&dWv, g_Wv);
    cudaGetSymbolAddress((void**)&dWo, g_Wo);

    const int nX4 = Mrows * Dm / 4;
    const int nW4 = Dm * Dm / 4;

    // 1) tf32 RN pre-rounding of all GEMM inputs
    round_tf32_kern<<<(nX4 + 255) / 256, 256>>>(query, dXq, nX4);
    round_tf32_kern<<<(nX4 + 255) / 256, 256>>>(key_,  dXk, nX4);
    round_tf32_kern<<<(nX4 + 255) / 256, 256>>>(value, dXv, nX4);
    round_tf32_kern<<<(nW4 + 255) / 256, 256>>>(w_q, dWq, nW4);
    round_tf32_kern<<<(nW4 + 255) / 256, 256>>>(w_k, dWk, nW4);
    round_tf32_kern<<<(nW4 + 255) / 256, 256>>>(w_v, dWv, nW4);
    round_tf32_kern<<<(nW4 + 255) / 256, 256>>>(w_o, dWo, nW4);

    // 2) QKV projections (mma.sync tf32) into head-split scratch
    gemm_qkv_tc<<<dim3(8, 64, 3), 256, GEMM_SMEM_BYTES>>>(b_q, b_k, b_v);

    // 3) attention (fp32 SIMT flash)
    attn_kernel<<<dim3(32, 64), 64>>>();

    // 4) output projection (mma.sync tf32) -> d_out
    gemm_out_tc<<<dim3(8, 64), 256, GEMM_SMEM_BYTES>>>(b_o, out);
}

// round 4
// speedup vs baseline: 3.5468x; 2.4624x over previous
#include <cuda_runtime.h>
#include <cstdint>

// Problem constants
#define Bsz 4
#define Ssz 2048
#define Hn  16
#define DKk 64
#define Dm  1024
#define Mrows (Bsz*Ssz)   // 8192

// ---------------- scratch (__device__ globals) ------------------------------
__device__ __align__(1024) float g_Q[(size_t)Bsz*Hn*Ssz*DKk];     // [B,H,S,dk] tf32-rounded
__device__ __align__(1024) float g_K[(size_t)Bsz*Hn*Ssz*DKk];
__device__ __align__(1024) float g_V[(size_t)Bsz*Hn*Ssz*DKk];
__device__ __align__(1024) float g_attn[(size_t)Mrows*Dm];        // [B*S, D] tf32-rounded
__device__ __align__(1024) float g_Xq[(size_t)Mrows*Dm];
__device__ __align__(1024) float g_Xk[(size_t)Mrows*Dm];
__device__ __align__(1024) float g_Xv[(size_t)Mrows*Dm];
__device__ __align__(1024) float g_Wq[(size_t)Dm*Dm];
__device__ __align__(1024) float g_Wk[(size_t)Dm*Dm];
__device__ __align__(1024) float g_Wv[(size_t)Dm*Dm];
__device__ __align__(1024) float g_Wo[(size_t)Dm*Dm];

// ---------------- helpers ----------------------------------------------------
__device__ __forceinline__ uint32_t smem_u32(const void* p) {
    uint32_t a;
    asm("{ .reg .u64 t; cvta.to.shared.u64 t, %1; cvt.u32.u64 %0, t; }" : "=r"(a) : "l"(p));
    return a;
}
__device__ __forceinline__ void cp_async16(uint32_t dst, const void* src) {
    asm volatile("cp.async.cg.shared.global [%0], [%1], 16;" :: "r"(dst), "l"(src));
}
#define CP_COMMIT() asm volatile("cp.async.commit_group;" ::: "memory")
#define CP_WAIT0()  asm volatile("cp.async.wait_group 0;" ::: "memory")

__device__ __forceinline__ float tf32_rn(float x) {
    uint32_t u;
    asm("cvt.rna.tf32.f32 %0, %1;" : "=r"(u) : "f"(x));
    return __uint_as_float(u);
}
__device__ __forceinline__ void mma_tf32(float* c, const uint32_t* a, uint32_t b0, uint32_t b1) {
    asm volatile(
        "mma.sync.aligned.m16n8k8.row.col.f32.tf32.tf32.f32 "
        "{%0,%1,%2,%3}, {%4,%5,%6,%7}, {%8,%9}, {%0,%1,%2,%3};"
        : "+f"(c[0]), "+f"(c[1]), "+f"(c[2]), "+f"(c[3])
        : "r"(a[0]), "r"(a[1]), "r"(a[2]), "r"(a[3]), "r"(b0), "r"(b1));
}

// ---------------------------------------------------------------------------
// mma.sync tf32 NT GEMM (unchanged from R3, plus tf32-RN rounding of the
// head-split outputs so the attention MMA sees exact operands)
// ---------------------------------------------------------------------------
#define LDA 36
#define GEMM_SMEM_BYTES (4 * 4608 * 4)

__device__ __forceinline__ void gemm_mma_body(const float* __restrict__ X,
                                              const float* __restrict__ W,
                                              const float* __restrict__ bias,
                                              float* __restrict__ out,
                                              int layout)
{
    extern __shared__ float sm[];
    float* Abuf[2] = { sm,        sm + 4608 };
    float* Bbuf[2] = { sm + 9216, sm + 13824 };

    const int tid  = threadIdx.x;
    const int lane = tid & 31, wid = tid >> 5;
    const int wm   = wid >> 2, wn = wid & 3;
    const int g    = lane >> 2, q = lane & 3;
    const int bm   = blockIdx.y * 128;
    const int bn   = blockIdx.x * 128;

    float acc[4][4][4];
#pragma unroll
    for (int i = 0; i < 4; i++)
#pragma unroll
        for (int j = 0; j < 4; j++)
#pragma unroll
            for (int k = 0; k < 4; k++) acc[i][j][k] = 0.f;

    auto issue_tile = [&](int kt, int buf) {
#pragma unroll
        for (int i = 0; i < 4; i++) {
            int idx = i * 256 + tid;
            int r = idx >> 3, c4 = idx & 7;
            cp_async16(smem_u32(&Abuf[buf][r * LDA + c4 * 4]),
                       X + (size_t)(bm + r) * Dm + kt * 32 + c4 * 4);
        }
#pragma unroll
        for (int i = 0; i < 4; i++) {
            int idx = i * 256 + tid;
            int r = idx >> 3, c4 = idx & 7;
            cp_async16(smem_u32(&Bbuf[buf][r * LDA + c4 * 4]),
                       W + (size_t)(bn + r) * Dm + kt * 32 + c4 * 4);
        }
        CP_COMMIT();
    };

    issue_tile(0, 0);
    CP_WAIT0();
    __syncthreads();

    const int NT = Dm / 32;
    for (int kt = 0; kt < NT; kt++) {
        int buf = kt & 1;
        if (kt + 1 < NT) issue_tile(kt + 1, buf ^ 1);

        const float* Ab = Abuf[buf];
        const float* Bb = Bbuf[buf];
#pragma unroll
        for (int ks = 0; ks < 4; ks++) {
            uint32_t afr[4][4], bfr[4][2];
#pragma unroll
            for (int mt = 0; mt < 4; mt++) {
                const float* pa = Ab + (wm * 64 + mt * 16 + g) * LDA + ks * 8 + q;
                afr[mt][0] = __float_as_uint(pa[0]);
                afr[mt][1] = __float_as_uint(pa[8 * LDA]);
                afr[mt][2] = __float_as_uint(pa[4]);
                afr[mt][3] = __float_as_uint(pa[8 * LDA + 4]);
            }
#pragma unroll
            for (int nt = 0; nt < 4; nt++) {
                const float* pb = Bb + (wn * 32 + nt * 8 + g) * LDA + ks * 8 + q;
                bfr[nt][0] = __float_as_uint(pb[0]);
                bfr[nt][1] = __float_as_uint(pb[4]);
            }
#pragma unroll
            for (int mt = 0; mt < 4; mt++)
#pragma unroll
                for (int nt = 0; nt < 4; nt++)
                    mma_tf32(acc[mt][nt], afr[mt], bfr[nt][0], bfr[nt][1]);
        }
        if (kt + 1 < NT) { CP_WAIT0(); __syncthreads(); }
    }

#pragma unroll
    for (int mt = 0; mt < 4; mt++) {
        int r0 = bm + wm * 64 + mt * 16 + g;
#pragma unroll
        for (int nt = 0; nt < 4; nt++) {
            int n = bn + wn * 32 + nt * 8 + q * 2;
            float2 v0, v1;
            if (layout) {   // head-split output feeds tf32 attention: RN-round
                v0.x = tf32_rn(acc[mt][nt][0] + bias[n]);
                v0.y = tf32_rn(acc[mt][nt][1] + bias[n + 1]);
                v1.x = tf32_rn(acc[mt][nt][2] + bias[n]);
                v1.y = tf32_rn(acc[mt][nt][3] + bias[n + 1]);
                int h = n >> 6, d = n & 63;
                int b0i = r0 >> 11, s0 = r0 & (Ssz - 1);
                int r1 = r0 + 8;
                int b1i = r1 >> 11, s1 = r1 & (Ssz - 1);
                *(float2*)&out[((size_t)((b0i * Hn + h) * Ssz + s0)) * DKk + d] = v0;
                *(float2*)&out[((size_t)((b1i * Hn + h) * Ssz + s1)) * DKk + d] = v1;
            } else {
                v0.x = acc[mt][nt][0] + bias[n];
                v0.y = acc[mt][nt][1] + bias[n + 1];
                v1.x = acc[mt][nt][2] + bias[n];
                v1.y = acc[mt][nt][3] + bias[n + 1];
                *(float2*)&out[(size_t)r0 * Dm + n] = v0;
                *(float2*)&out[(size_t)(r0 + 8) * Dm + n] = v1;
            }
        }
    }
}

__global__ __launch_bounds__(256, 2) void gemm_qkv_tc(const float* __restrict__ bq,
                                                      const float* __restrict__ bk,
                                                      const float* __restrict__ bv)
{
    const float* X; const float* W; const float* bias; float* out;
    if (blockIdx.z == 0)      { X = g_Xq; W = g_Wq; bias = bq; out = g_Q; }
    else if (blockIdx.z == 1) { X = g_Xk; W = g_Wk; bias = bk; out = g_K; }
    else                      { X = g_Xv; W = g_Wv; bias = bv; out = g_V; }
    gemm_mma_body(X, W, bias, out, 1);
}

__global__ __launch_bounds__(256, 2) void gemm_out_tc(const float* __restrict__ bo,
                                                      float* __restrict__ out)
{
    gemm_mma_body(g_attn, g_Wo, bo, out, 0);
}

// ---------------------------------------------------------------------------
// tf32 RN pre-rounding of GEMM inputs
// ---------------------------------------------------------------------------
__global__ __launch_bounds__(256) void round_tf32_kern(const float* __restrict__ s,
                                                       float* __restrict__ d, int n4)
{
    int i = blockIdx.x * blockDim.x + threadIdx.x;
    if (i >= n4) return;
    float4 v = ((const float4*)s)[i];
    float4 o;
    o.x = tf32_rn(v.x); o.y = tf32_rn(v.y);
    o.z = tf32_rn(v.z); o.w = tf32_rn(v.w);
    ((float4*)d)[i] = o;
}

// ---------------------------------------------------------------------------
// Flash attention with mma.sync tf32.
// CTA = (q-tile 64 rows, bh). 4 warps; warp w owns rows w*16..w*16+15.
// K tile (64 keys x 64 d) in SMEM via cp.async; V staged transposed Vt[d][key];
// P (probs) staged per-warp in SMEM to re-feed as A fragments.
// ---------------------------------------------------------------------------
#define LDK 68
#define ATT_SMEM (3 * 64 * LDK * 4)   // Ks + Vt + Ps = 52224 B

__global__ __launch_bounds__(128) void attn_mma_kernel()
{
    extern __shared__ float smf[];
    float* Ks = smf;                 // [64][LDK]  K tile, rows = key, cols = d
    float* Vt = smf + 64 * LDK;      // [64][LDK]  V tile transposed: rows = d, cols = key
    float* Ps = smf + 2 * 64 * LDK;  // [64][LDK]  probs, rows = local q row

    const int bh = blockIdx.y;
    const int qb = blockIdx.x * 64;
    const int tid = threadIdx.x;
    const int lane = tid & 31, w = tid >> 5;
    const int g = lane >> 2, q = lane & 3;

    const float* Qb = g_Q + (size_t)bh * Ssz * DKk;
    const float* Kb = g_K + (size_t)bh * Ssz * DKk;
    const float* Vb = g_V + (size_t)bh * Ssz * DKk;

    // ---- stage Q tile (scaled by 1/8, exact) into Ks, then grab fragments --
#pragma unroll
    for (int i = 0; i < 8; i++) {
        int idx = i * 128 + tid;
        int r = idx >> 4, c = (idx & 15) * 4;
        float4 v = *(const float4*)&Qb[(size_t)(qb + r) * DKk + c];
        v.x *= 0.125f; v.y *= 0.125f; v.z *= 0.125f; v.w *= 0.125f;
        *(float4*)&Ks[r * LDK + c] = v;
    }
    __syncthreads();

    uint32_t qfr[8][4];
#pragma unroll
    for (int ks = 0; ks < 8; ks++) {
        const float* pa = &Ks[(w * 16 + g) * LDK + ks * 8 + q];
        qfr[ks][0] = __float_as_uint(pa[0]);
        qfr[ks][1] = __float_as_uint(pa[8 * LDK]);
        qfr[ks][2] = __float_as_uint(pa[4]);
        qfr[ks][3] = __float_as_uint(pa[8 * LDK + 4]);
    }

    float oacc[8][4];
#pragma unroll
    for (int nt = 0; nt < 8; nt++)
#pragma unroll
        for (int k = 0; k < 4; k++) oacc[nt][k] = 0.f;
    float mA = -1e30f, mB = -1e30f, lA = 0.f, lB = 0.f;

    for (int kt = 0; kt < Ssz / 64; kt++) {
        const int base = kt * 64;
        __syncthreads();   // everyone done reading Ks/Vt (or Q-frag phase)

        // K tile: cp.async straight in
#pragma unroll
        for (int i = 0; i < 8; i++) {
            int idx = i * 128 + tid;
            int r = idx >> 4, c = (idx & 15) * 4;
            cp_async16(smem_u32(&Ks[r * LDK + c]), &Kb[(size_t)(base + r) * DKk + c]);
        }
        CP_COMMIT();
        // V tile: load + transpose store
#pragma unroll
        for (int i = 0; i < 8; i++) {
            int idx = i * 128 + tid;
            int r = idx >> 4, c = (idx & 15) * 4;
            float4 v = *(const float4*)&Vb[(size_t)(base + r) * DKk + c];
            Vt[(c + 0) * LDK + r] = v.x;
            Vt[(c + 1) * LDK + r] = v.y;
            Vt[(c + 2) * LDK + r] = v.z;
            Vt[(c + 3) * LDK + r] = v.w;
        }
        CP_WAIT0();
        __syncthreads();

        // ---- S = Q * K^T : warp computes 16 x 64 ----
        float sacc[8][4];
#pragma unroll
        for (int nt = 0; nt < 8; nt++)
#pragma unroll
            for (int k = 0; k < 4; k++) sacc[nt][k] = 0.f;
#pragma unroll
        for (int nt = 0; nt < 8; nt++) {
#pragma unroll
            for (int ks = 0; ks < 8; ks++) {
                const float* pb = &Ks[(nt * 8 + g) * LDK + ks * 8 + q];
                mma_tf32(sacc[nt], qfr[ks],
                         __float_as_uint(pb[0]), __float_as_uint(pb[4]));
            }
        }

        // ---- online softmax (rows g and g+8 per thread) ----
        float mtA = -1e30f, mtB = -1e30f;
#pragma unroll
        for (int nt = 0; nt < 8; nt++) {
            mtA = fmaxf(mtA, fmaxf(sacc[nt][0], sacc[nt][1]));
            mtB = fmaxf(mtB, fmaxf(sacc[nt][2], sacc[nt][3]));
        }
        mtA = fmaxf(mtA, __shfl_xor_sync(0xffffffffu, mtA, 1));
        mtA = fmaxf(mtA, __shfl_xor_sync(0xffffffffu, mtA, 2));
        mtB = fmaxf(mtB, __shfl_xor_sync(0xffffffffu, mtB, 1));
        mtB = fmaxf(mtB, __shfl_xor_sync(0xffffffffu, mtB, 2));

        float mnA = fmaxf(mA, mtA), mnB = fmaxf(mB, mtB);
        float corrA = __expf(mA - mnA), corrB = __expf(mB - mnB);
        mA = mnA; mB = mnB;

        float sA = 0.f, sB = 0.f;
        float* prowA = &Ps[(w * 16 + g) * LDK];
        float* prowB = &Ps[(w * 16 + g + 8) * LDK];
#pragma unroll
        for (int nt = 0; nt < 8; nt++) {
            float p0 = __expf(sacc[nt][0] - mA);
            float p1 = __expf(sacc[nt][1] - mA);
            float p2 = __expf(sacc[nt][2] - mB);
            float p3 = __expf(sacc[nt][3] - mB);
            sA += p0 + p1;
            sB += p2 + p3;
            float2 vA = { tf32_rn(p0), tf32_rn(p1) };
            float2 vB = { tf32_rn(p2), tf32_rn(p3) };
            *(float2*)&prowA[nt * 8 + q * 2] = vA;
            *(float2*)&prowB[nt * 8 + q * 2] = vB;
        }
        sA += __shfl_xor_sync(0xffffffffu, sA, 1);
        sA += __shfl_xor_sync(0xffffffffu, sA, 2);
        sB += __shfl_xor_sync(0xffffffffu, sB, 1);
        sB += __shfl_xor_sync(0xffffffffu, sB, 2);
        lA = lA * corrA + sA;
        lB = lB * corrB + sB;

#pragma unroll
        for (int nt = 0; nt < 8; nt++) {
            oacc[nt][0] *= corrA; oacc[nt][1] *= corrA;
            oacc[nt][2] *= corrB; oacc[nt][3] *= corrB;
        }
        __syncwarp();

        // ---- O += P * V ----
#pragma unroll
        for (int ks = 0; ks < 8; ks++) {
            uint32_t afr[4];
            const float* pa = &Ps[(w * 16 + g) * LDK + ks * 8 + q];
            afr[0] = __float_as_uint(pa[0]);
            afr[1] = __float_as_uint(pa[8 * LDK]);
            afr[2] = __float_as_uint(pa[4]);
            afr[3] = __float_as_uint(pa[8 * LDK + 4]);
#pragma unroll
            for (int nt = 0; nt < 8; nt++) {
                const float* pb = &Vt[(nt * 8 + g) * LDK + ks * 8 + q];
                mma_tf32(oacc[nt], afr,
                         __float_as_uint(pb[0]), __float_as_uint(pb[4]));
            }
        }
    }

    // ---- epilogue: normalize, tf32-RN round, write to g_attn -------------
    float invA = 1.f / lA, invB = 1.f / lB;
    int b = bh >> 4, h = bh & 15;
    int row0 = qb + w * 16 + g;
    int row1 = row0 + 8;
#pragma unroll
    for (int nt = 0; nt < 8; nt++) {
        int col = h * DKk + nt * 8 + q * 2;
        float2 v0 = { tf32_rn(oacc[nt][0] * invA), tf32_rn(oacc[nt][1] * invA) };
        float2 v1 = { tf32_rn(oacc[nt][2] * invB), tf32_rn(oacc[nt][3] * invB) };
        *(float2*)&g_attn[(size_t)(b * Ssz + row0) * Dm + col] = v0;
        *(float2*)&g_attn[(size_t)(b * Ssz + row1) * Dm + col] = v1;
    }
}

// ---------------------------------------------------------------------------
extern "C" void kernel_launch(void* const* d_in, const int* in_sizes, int n_in,
                              void* d_out, int out_size)
{
    const float* query = (const float*)d_in[0];
    const float* key_  = (const float*)d_in[1];
    const float* value = (const float*)d_in[2];
    const float* w_q   = (const float*)d_in[3];
    const float* b_q   = (const float*)d_in[4];
    const float* w_k   = (const float*)d_in[5];
    const float* b_k   = (const float*)d_in[6];
    const float* w_v   = (const float*)d_in[7];
    const float* b_v   = (const float*)d_in[8];
    const float* w_o   = (const float*)d_in[9];
    const float* b_o   = (const float*)d_in[10];
    float* out = (float*)d_out;

    cudaFuncSetAttribute(gemm_qkv_tc, cudaFuncAttributeMaxDynamicSharedMemorySize, GEMM_SMEM_BYTES);
    cudaFuncSetAttribute(gemm_out_tc, cudaFuncAttributeMaxDynamicSharedMemorySize, GEMM_SMEM_BYTES);
    cudaFuncSetAttribute(attn_mma_kernel, cudaFuncAttributeMaxDynamicSharedMemorySize, ATT_SMEM);

    float *dXq, *dXk, *dXv, *dWq, *dWk, *dWv, *dWo;
    cudaGetSymbolAddress((void**)&dXq, g_Xq);
    cudaGetSymbolAddress((void**)&dXk, g_Xk);
    cudaGetSymbolAddress((void**)&dXv, g_Xv);
    cudaGetSymbolAddress((void**)&dWq, g_Wq);
    cudaGetSymbolAddress((void**)&dWk, g_Wk);
    cudaGetSymbolAddress((void**)&dWv, g_Wv);
    cudaGetSymbolAddress((void**)&dWo, g_Wo);

    const int nX4 = Mrows * Dm / 4;
    const int nW4 = Dm * Dm / 4;

    round_tf32_kern<<<(nX4 + 255) / 256, 256>>>(query, dXq, nX4);
    round_tf32_kern<<<(nX4 + 255) / 256, 256>>>(key_,  dXk, nX4);
    round_tf32_kern<<<(nX4 + 255) / 256, 256>>>(value, dXv, nX4);
    round_tf32_kern<<<(nW4 + 255) / 256, 256>>>(w_q, dWq, nW4);
    round_tf32_kern<<<(nW4 + 255) / 256, 256>>>(w_k, dWk, nW4);
    round_tf32_kern<<<(nW4 + 255) / 256, 256>>>(w_v, dWv, nW4);
    round_tf32_kern<<<(nW4 + 255) / 256, 256>>>(w_o, dWo, nW4);

    gemm_qkv_tc<<<dim3(8, 64, 3), 256, GEMM_SMEM_BYTES>>>(b_q, b_k, b_v);

    attn_mma_kernel<<<dim3(32, 64), 128, ATT_SMEM>>>();

    gemm_out_tc<<<dim3(8, 64), 256, GEMM_SMEM_BYTES>>>(b_o, out);
}